// round 16
// baseline (speedup 1.0000x reference)
#include <cuda_runtime.h>
#include <cuda_fp16.h>
#include <cstdint>
#include <cstddef>

#define NE    160000
#define NN    10000
#define HID   300
#define PAD   320
#define LDIM  32
#define MRWS  160000
#define NGRP  16

#define LOWBLK 79                   // m-blocks covering rows [0, 10112) > NN
#define LOWROW (LOWBLK * 128)       // 10112

// ---------------- scratch (static __device__, allocation-free) ----------------
__device__ __half g_bufA[(size_t)MRWS * PAD];   // 102.4 MB (fp16 activations, post-relu)
__device__ __half g_bufB[(size_t)MRWS * PAD];   // 102.4 MB
__device__ float  g_hwS[(size_t)NN * PAD];      // 12.8 MB raw hw, rows < NN (fp32)
__device__ __half g_BT[(size_t)NGRP * 5 * PAD * PAD];  // [group][layer][n][k] fp16
__device__ int    g_cnt[NN];
__device__ float  g_dinv[NN];
__device__ int    g_rowptr[NN + 1];
__device__ int    g_fill[NN];
__device__ int    g_eid[NE];
__device__ int    g_src[NE];
__device__ float  g_val[NE];
__device__ float  g_part[625 * PAD];

#define MMA_F16(c, a, b)                                                      \
    asm volatile("mma.sync.aligned.m16n8k16.row.col.f32.f16.f16.f32 "         \
        "{%0,%1,%2,%3}, {%4,%5,%6,%7}, {%8,%9}, {%0,%1,%2,%3};"               \
        : "+f"((c)[0]), "+f"((c)[1]), "+f"((c)[2]), "+f"((c)[3])              \
        : "r"((a)[0]), "r"((a)[1]), "r"((a)[2]), "r"((a)[3]),                 \
          "r"((b)[0]), "r"((b)[1]))

#define LDSM4(r0, r1, r2, r3, addr)                                           \
    asm volatile("ldmatrix.sync.aligned.m8n8.x4.shared.b16 {%0,%1,%2,%3}, [%4];" \
        : "=r"(r0), "=r"(r1), "=r"(r2), "=r"(r3) : "r"(addr))

__device__ __forceinline__ uint32_t smem_u32(const void* p) {
    uint32_t a;
    asm("{ .reg .u64 t; cvta.to.shared.u64 t, %1; cvt.u32.u64 %0, t; }" : "=r"(a) : "l"(p));
    return a;
}
__device__ __forceinline__ void cp16(uint32_t dst, const void* src) {
    asm volatile("cp.async.cg.shared.global [%0], [%1], 16;" :: "r"(dst), "l"(src));
}
#define CP_COMMIT() asm volatile("cp.async.commit_group;" ::: "memory")
#define CP_WAIT(n)  asm volatile("cp.async.wait_group %0;" :: "n"(n) : "memory")

// ---------------- prep kernels ----------------
__global__ void k_init() {
    int i = blockIdx.x * blockDim.x + threadIdx.x;
    if (i < NN) { g_cnt[i] = 0; g_fill[i] = 0; }
}
__global__ void k_count(const int* __restrict__ ei) {
    int e = blockIdx.x * blockDim.x + threadIdx.x;
    if (e < NE) atomicAdd(&g_cnt[ei[NE + e]], 1);
}
__global__ void k_dinv() {
    int i = blockIdx.x * blockDim.x + threadIdx.x;
    if (i < NN) g_dinv[i] = rsqrtf((float)(g_cnt[i] + 1));
}
__global__ void k_scan() {
    __shared__ int sm[1024];
    int t = threadIdx.x;
    int v[10]; int loc = 0;
#pragma unroll
    for (int u = 0; u < 10; u++) {
        int idx = t * 10 + u;
        v[u] = (idx < NN) ? g_cnt[idx] : 0;
        loc += v[u];
    }
    sm[t] = loc; __syncthreads();
    for (int off = 1; off < 1024; off <<= 1) {
        int add = (t >= off) ? sm[t - off] : 0;
        __syncthreads();
        sm[t] += add;
        __syncthreads();
    }
    int run = sm[t] - loc;
#pragma unroll
    for (int u = 0; u < 10; u++) {
        int idx = t * 10 + u;
        if (idx < NN) { g_rowptr[idx] = run; run += v[u]; }
    }
    if (t == 0) g_rowptr[NN] = NE;
}
__global__ void k_fillidx(const int* __restrict__ ei) {
    int e = blockIdx.x * blockDim.x + threadIdx.x;
    if (e >= NE) return;
    int c = ei[NE + e];
    int p = atomicAdd(&g_fill[c], 1);
    g_eid[g_rowptr[c] + p] = e;
}
// deterministic per-node ordering: sort edge ids ascending
__global__ void k_sortnode(const int* __restrict__ ei) {
    int i = blockIdx.x * blockDim.x + threadIdx.x;
    if (i >= NN) return;
    int s = g_rowptr[i], d = g_rowptr[i + 1] - s;
    if (d <= 128) {
        int ids[128];
        for (int q = 0; q < d; q++) ids[q] = g_eid[s + q];
        for (int q = 1; q < d; q++) {
            int key = ids[q], p = q - 1;
            while (p >= 0 && ids[p] > key) { ids[p + 1] = ids[p]; p--; }
            ids[p + 1] = key;
        }
        for (int q = 0; q < d; q++) g_eid[s + q] = ids[q];
    } else {
        for (int q = 1; q < d; q++) {
            int key = g_eid[s + q], p = q - 1;
            while (p >= 0 && g_eid[s + p] > key) { g_eid[s + p + 1] = g_eid[s + p]; p--; }
            g_eid[s + p + 1] = key;
        }
    }
    float di = g_dinv[i];
    for (int q = 0; q < d; q++) {
        int e = g_eid[s + q];
        int r = ei[e];
        g_src[s + q] = r;
        g_val[s + q] = g_dinv[r] * di;
    }
}
// edge embed over edge-row range [e0, e0+ecnt)
__global__ void k_edge_embed(const float* __restrict__ attr,
                             const float* __restrict__ w,
                             const float* __restrict__ b, int e0, int ecnt) {
    int idx = blockIdx.x * blockDim.x + threadIdx.x;
    if (idx >= ecnt * LDIM) return;
    int e = e0 + (idx >> 5), j = idx & 31;
    float a0 = attr[e * 3 + 0], a1 = attr[e * 3 + 1], a2 = attr[e * 3 + 2];
    float s = b[j] + a0 * w[j] + a1 * w[32 + j] + a2 * w[64 + j];
    g_bufA[(size_t)e * PAD + j] = __float2half_rn(s);
}
// Weights -> NGRP fp16 copies via error-feedback rounding (group means -> w),
// transposed [n][k], padded to 320.
__global__ void k_prepB(const float* __restrict__ gcn0_w, const float* __restrict__ gcn_w) {
    int idx = blockIdx.x * blockDim.x + threadIdx.x;   // 5*320*320
    if (idx >= 5 * PAD * PAD) return;
    int l   = idx / (PAD * PAD);
    int rem = idx % (PAD * PAD);
    int n   = rem / PAD;
    int k   = rem % PAD;
    int kt  = (l == 0) ? LDIM : HID;
    float w = 0.f;
    if (k < kt && n < HID)
        w = (l == 0) ? gcn0_w[k * HID + n]
                     : gcn_w[(size_t)(l - 1) * HID * HID + k * HID + n];
    float e = 0.f;
    size_t off = (size_t)l * PAD * PAD + (size_t)n * PAD + k;
#pragma unroll
    for (int g = 0; g < NGRP; g++) {
        float t = w + e;
        __half h = __float2half_rn(t);
        e = t - __half2float(h);
        g_BT[(size_t)g * 5 * PAD * PAD + off] = h;
    }
}

// ---------------- fp16 mma.sync GEMM (group-rounded weights) ----------------
// BM=128, BN=160, grid (2, mblks): blockIdx.x = n-block FAST -> both n-blocks
// of an A row-block co-resident (A dedups in L2).  Weight copy chosen by
// (m-block + layer) & 15 -> per-row errors decorrelate across layers AND
// average across groups at the mean readout.  256 threads (8 warps 4m x 2n),
// warp tile 32x80: 7 LDSM.x4 -> 20 MMAs per k16-step.
// 3-stage cp.async pipeline, SINGLE __syncthreads per chunk (R8 pattern).
#define AW_STR   20
#define A_ST     (128 * AW_STR)          // 2560 words per A stage
#define B_BASE   (3 * A_ST)              // 7680
#define B_ST     (160 * AW_STR)          // 3200 words per B stage
#define SMW      (B_BASE + 3 * B_ST)     // 17280 words = 69120 B
#define GSTRIDE  ((size_t)5 * PAD * PAD)

__global__ __launch_bounds__(256, 2)
void k_gemm(const __half* __restrict__ A, const __half* __restrict__ BT,
            const float* __restrict__ bias, __half* __restrict__ out,
            int Ksteps, int mblk0, int lidx) {
    extern __shared__ uint32_t smu[];
    const uint32_t sb = smem_u32(smu);
    const int tid  = threadIdx.x;
    const int wid  = tid >> 5, lane = tid & 31;
    const int wm   = wid & 3, wn = wid >> 2;
    const int mblk = (int)blockIdx.y + mblk0;
    const size_t m0 = (size_t)mblk * 128;
    const int    n0 = blockIdx.x * 160;
    const __half* B = BT + (size_t)((mblk + lidx) & (NGRP - 1)) * GSTRIDE
                         + (size_t)lidx * PAD * PAD;
    const int NC = (Ksteps + 1) >> 1;

    float acc[2][10][4];
#pragma unroll
    for (int t = 0; t < 2; t++)
#pragma unroll
        for (int j = 0; j < 10; j++)
#pragma unroll
            for (int q = 0; q < 4; q++) acc[t][j][q] = 0.f;

    // ldmatrix per-thread offsets (bytes, relative to stage base)
    const int g = lane >> 3, l7 = lane & 7;
    uint32_t aoff[2], boff[5];
#pragma unroll
    for (int t = 0; t < 2; t++)
        aoff[t] = 4u * ((wm * 32 + t * 16 + (g & 1) * 8 + l7) * AW_STR + (g >> 1) * 4);
#pragma unroll
    for (int jp = 0; jp < 5; jp++)
        boff[jp] = 4u * ((wn * 80 + jp * 16 + (g >> 1) * 8 + l7) * AW_STR + (g & 1) * 4);

    // cp.async segment mapping: A 512 segs (2/thread), B 640 segs (<=3/thread)
    const int a_row0 = tid >> 2, a_seg = tid & 3;
    auto issue = [&](int st, int c) {
        int k0 = c * 32;
        uint32_t ab = sb + (uint32_t)(st * A_ST) * 4;
#pragma unroll
        for (int u = 0; u < 2; u++) {
            int row = a_row0 + u * 64;
            cp16(ab + (uint32_t)(row * AW_STR + a_seg * 4) * 4,
                 A + (m0 + row) * PAD + k0 + a_seg * 8);
        }
        uint32_t bb = sb + (uint32_t)(B_BASE + st * B_ST) * 4;
#pragma unroll
        for (int u = 0; u < 3; u++) {
            int s = tid + u * 256;
            if (s < 640) {
                int row = s >> 2, seg = s & 3;
                cp16(bb + (uint32_t)(row * AW_STR + seg * 4) * 4,
                     B + (size_t)(n0 + row) * PAD + k0 + seg * 8);
            }
        }
        CP_COMMIT();
    };

    auto compute = [&](int st, int nks) {
        uint32_t ab = sb + (uint32_t)(st * A_ST) * 4;
        uint32_t bb = sb + (uint32_t)(B_BASE + st * B_ST) * 4;
#pragma unroll
        for (int ks = 0; ks < 2; ks++) {
            if (ks >= nks) break;
            uint32_t ko = (uint32_t)ks * 32;   // 8 words
            uint32_t af[2][4];
            LDSM4(af[0][0], af[0][1], af[0][2], af[0][3], ab + aoff[0] + ko);
            LDSM4(af[1][0], af[1][1], af[1][2], af[1][3], ab + aoff[1] + ko);
            uint32_t bf[10][2];
#pragma unroll
            for (int jp = 0; jp < 5; jp++)
                LDSM4(bf[2 * jp][0], bf[2 * jp][1], bf[2 * jp + 1][0], bf[2 * jp + 1][1],
                      bb + boff[jp] + ko);
#pragma unroll
            for (int t = 0; t < 2; t++)
#pragma unroll
                for (int j = 0; j < 10; j++)
                    MMA_F16(acc[t][j], af[t], bf[j]);
        }
    };

    issue(0, 0);
    if (NC > 1) issue(1, 1);
    for (int c = 0; c < NC; c++) {
        if (c == NC - 1) { CP_WAIT(0); } else { CP_WAIT(1); }
        __syncthreads();
        if (c + 2 < NC) issue((c + 2) % 3, c + 2);
        compute(c % 3, Ksteps - 2 * c);
    }

    // ---- epilogue ----
    const int lr = lane >> 2, lc = lane & 3;
#pragma unroll
    for (int t = 0; t < 2; t++) {
        size_t r0 = m0 + wm * 32 + t * 16 + lr;
        size_t r1 = r0 + 8;
        bool nd0 = r0 < NN, nd1 = r1 < NN;
        float sn0 = 1.f, sn1 = 1.f;
        if (nd0) { float dv = g_dinv[r0]; sn0 = dv * dv; }
        if (nd1) { float dv = g_dinv[r1]; sn1 = dv * dv; }
#pragma unroll
        for (int j = 0; j < 10; j++) {
            int col = n0 + wn * 80 + j * 8 + lc * 2;
            float b0 = (col     < HID) ? bias[col]     : 0.f;
            float b1 = (col + 1 < HID) ? bias[col + 1] : 0.f;
            float c0 = acc[t][j][0], c1 = acc[t][j][1];
            float c2 = acc[t][j][2], c3 = acc[t][j][3];
            float o0 = fmaf(sn0, c0, b0), o1 = fmaf(sn0, c1, b1);
            float o2 = fmaf(sn1, c2, b0), o3 = fmaf(sn1, c3, b1);
            if (!nd0) { o0 = fmaxf(o0, 0.f); o1 = fmaxf(o1, 0.f); }
            if (!nd1) { o2 = fmaxf(o2, 0.f); o3 = fmaxf(o3, 0.f); }
            *(__half2*)(out + r0 * PAD + col) = __floats2half2_rn(o0, o1);
            *(__half2*)(out + r1 * PAD + col) = __floats2half2_rn(o2, o3);
            if (nd0) *(float2*)(g_hwS + r0 * PAD + col) = make_float2(c0, c1);
            if (nd1) *(float2*)(g_hwS + r1 * PAD + col) = make_float2(c2, c3);
        }
    }
}

// -------- CSR gather: out[node] = relu(out[node] + sum val * hw[src]) --------
__global__ __launch_bounds__(256)
void k_gather(__half* __restrict__ out) {
    int w = (blockIdx.x * 256 + threadIdx.x) >> 5;
    int lane = threadIdx.x & 31;
    if (w >= NN * 10) return;
    int node = w / 10, seg = w % 10;
    int j = seg * 32 + lane;
    int s = g_rowptr[node], e = g_rowptr[node + 1];
    float acc = __half2float(out[(size_t)node * PAD + j]);
    for (int p = s; p < e; p++)
        acc = fmaf(g_val[p], g_hwS[(size_t)g_src[p] * PAD + j], acc);
    out[(size_t)node * PAD + j] = __float2half_rn(fmaxf(acc, 0.f));
}

// ---------------- readout ----------------
__global__ void k_mean(const __half* __restrict__ h) {
    int j = threadIdx.x;  // 320
    size_t r0 = (size_t)blockIdx.x * 256;
    float acc = 0.f;
    for (int r = 0; r < 256; r++)
        acc += fmaxf(__half2float(h[(r0 + r) * PAD + j]), 0.f);
    g_part[blockIdx.x * PAD + j] = acc;
}
__global__ void k_head(const float* __restrict__ w1, const float* __restrict__ b1,
                       const float* __restrict__ w2, const float* __restrict__ b2,
                       float* __restrict__ out) {
    __shared__ float g[PAD];
    __shared__ float t1[32];
    int t = threadIdx.x;  // 320
    if (t < PAD) {
        float s = 0.f;
        for (int b = 0; b < 625; b++) s += g_part[b * PAD + t];
        g[t] = s * (1.0f / (float)MRWS);
    }
    __syncthreads();
    if (t < 32) {
        float a = b1[t];
        for (int j = 0; j < HID; j++) a = fmaf(g[j], w1[j * 32 + t], a);
        t1[t] = fmaxf(a, 0.f);
    }
    __syncthreads();
    if (t < 2) {
        float a = b2[t];
        for (int k = 0; k < 32; k++) a = fmaf(t1[k], w2[k * 2 + t], a);
        out[t] = a;
    }
}

// ---------------- launch ----------------
extern "C" void kernel_launch(void* const* d_in, const int* in_sizes, int n_in,
                              void* d_out, int out_size) {
    const int*   ei        = (const int*)d_in[1];
    const float* edge_attr = (const float*)d_in[2];
    const float* edge_w    = (const float*)d_in[6];
    const float* edge_b    = (const float*)d_in[7];
    const float* gcn0_w    = (const float*)d_in[8];
    const float* gcn0_b    = (const float*)d_in[9];
    const float* gcn_w     = (const float*)d_in[10];
    const float* gcn_b     = (const float*)d_in[11];
    const float* lin1_w    = (const float*)d_in[12];
    const float* lin1_b    = (const float*)d_in[13];
    const float* lin2_w    = (const float*)d_in[14];
    const float* lin2_b    = (const float*)d_in[15];
    float* out = (float*)d_out;

    // one-time host infra (streams/events; no device memory)
    static cudaStream_t sB = nullptr;
    static cudaEvent_t evFork = nullptr, evJoin = nullptr;
    if (!sB) {
        cudaStreamCreateWithFlags(&sB, cudaStreamNonBlocking);
        cudaEventCreateWithFlags(&evFork, cudaEventDisableTiming);
        cudaEventCreateWithFlags(&evJoin, cudaEventDisableTiming);
        cudaFuncSetAttribute(k_gemm, cudaFuncAttributeMaxDynamicSharedMemorySize, SMW * 4);
    }

    __half *bufA = nullptr, *bufB = nullptr, *bt = nullptr;
    cudaGetSymbolAddress((void**)&bufA, g_bufA);
    cudaGetSymbolAddress((void**)&bufB, g_bufB);
    cudaGetSymbolAddress((void**)&bt, g_BT);

    const int EHI = NE - LOWROW;                      // 149888 high edges

    // --- shared prologue on capture stream: weights (needed by both chains) ---
    k_prepB<<<2000, 256>>>(gcn0_w, gcn_w);

    // --- fork: high chain (rows >= LOWROW) on sB ---
    cudaEventRecord(evFork, 0);
    cudaStreamWaitEvent(sB, evFork, 0);

    k_edge_embed<<<(EHI * LDIM + 255) / 256, 256, 0, sB>>>(edge_attr, edge_w, edge_b,
                                                           LOWROW, EHI);
    {
        dim3 ghi(2, 1250 - LOWBLK);
        k_gemm<<<ghi, 256, SMW * 4, sB>>>(bufA, bt, gcn0_b, bufB, 2, LOWBLK, 0);
        for (int l = 1; l < 5; l++) {
            const __half* in = (l & 1) ? bufB : bufA;
            __half*       o  = (l & 1) ? bufA : bufB;
            k_gemm<<<ghi, 256, SMW * 4, sB>>>(in, bt, gcn_b + (size_t)(l - 1) * HID,
                                              o, 19, LOWBLK, l);
        }
    }
    cudaEventRecord(evJoin, sB);

    // --- low chain (rows < LOWROW) + CSR machinery on capture stream ---
    k_init<<<40, 256>>>();
    k_count<<<625, 256>>>(ei);
    k_dinv<<<40, 256>>>();
    k_scan<<<1, 1024>>>();
    k_fillidx<<<625, 256>>>(ei);
    k_sortnode<<<40, 256>>>(ei);
    k_edge_embed<<<(LOWROW * LDIM + 255) / 256, 256>>>(edge_attr, edge_w, edge_b,
                                                       0, LOWROW);
    {
        dim3 glo(2, LOWBLK);
        k_gemm<<<glo, 256, SMW * 4>>>(bufA, bt, gcn0_b, bufB, 2, 0, 0);
        k_gather<<<12500, 256>>>(bufB);
        for (int l = 1; l < 5; l++) {
            const __half* in = (l & 1) ? bufB : bufA;
            __half*       o  = (l & 1) ? bufA : bufB;
            k_gemm<<<glo, 256, SMW * 4>>>(in, bt, gcn_b + (size_t)(l - 1) * HID,
                                          o, 19, 0, l);
            k_gather<<<12500, 256>>>(o);
        }
    }

    // --- join and readout ---
    cudaStreamWaitEvent(0, evJoin, 0);
    k_mean<<<625, 320>>>(bufB);
    k_head<<<1, 320>>>(lin1_w, lin1_b, lin2_w, lin2_b, out);
}

// round 17
// speedup vs baseline: 1.0550x; 1.0550x over previous
#include <cuda_runtime.h>
#include <cuda_fp16.h>
#include <cstdint>
#include <cstddef>

#define NE    160000
#define NN    10000
#define HID   300
#define PAD   320
#define LDIM  32
#define MRWS  160000
#define NGRP  16

#define LOWBLK 79                   // m-blocks covering rows [0, 10112) > NN
#define LOWROW (LOWBLK * 128)       // 10112

// ---------------- scratch (static __device__, allocation-free) ----------------
__device__ __half g_bufA[(size_t)MRWS * PAD];   // 102.4 MB (fp16 activations, post-relu)
__device__ __half g_bufB[(size_t)MRWS * PAD];   // 102.4 MB
__device__ float  g_hwS[(size_t)NN * PAD];      // 12.8 MB raw hw, rows < NN (fp32)
__device__ __half g_BT[(size_t)NGRP * 5 * PAD * PAD];  // [group][layer][n][k] fp16
__device__ int    g_cnt[NN];
__device__ float  g_dinv[NN];
__device__ int    g_rowptr[NN + 1];
__device__ int    g_fill[NN];
__device__ int    g_eid[NE];
__device__ int    g_src[NE];
__device__ float  g_val[NE];
__device__ float  g_part[625 * PAD];

#define MMA_F16(c, a, b)                                                      \
    asm volatile("mma.sync.aligned.m16n8k16.row.col.f32.f16.f16.f32 "         \
        "{%0,%1,%2,%3}, {%4,%5,%6,%7}, {%8,%9}, {%0,%1,%2,%3};"               \
        : "+f"((c)[0]), "+f"((c)[1]), "+f"((c)[2]), "+f"((c)[3])              \
        : "r"((a)[0]), "r"((a)[1]), "r"((a)[2]), "r"((a)[3]),                 \
          "r"((b)[0]), "r"((b)[1]))

#define LDSM4(r0, r1, r2, r3, addr)                                           \
    asm volatile("ldmatrix.sync.aligned.m8n8.x4.shared.b16 {%0,%1,%2,%3}, [%4];" \
        : "=r"(r0), "=r"(r1), "=r"(r2), "=r"(r3) : "r"(addr))

__device__ __forceinline__ uint32_t smem_u32(const void* p) {
    uint32_t a;
    asm("{ .reg .u64 t; cvta.to.shared.u64 t, %1; cvt.u32.u64 %0, t; }" : "=r"(a) : "l"(p));
    return a;
}
__device__ __forceinline__ void cp16(uint32_t dst, const void* src) {
    asm volatile("cp.async.cg.shared.global [%0], [%1], 16;" :: "r"(dst), "l"(src));
}
#define CP_COMMIT() asm volatile("cp.async.commit_group;" ::: "memory")
#define CP_WAIT(n)  asm volatile("cp.async.wait_group %0;" :: "n"(n) : "memory")

// ---------------- prep kernels ----------------
__global__ void k_init() {
    int i = blockIdx.x * blockDim.x + threadIdx.x;
    if (i < NN) { g_cnt[i] = 0; g_fill[i] = 0; }
}
__global__ void k_count(const int* __restrict__ ei) {
    int e = blockIdx.x * blockDim.x + threadIdx.x;
    if (e < NE) atomicAdd(&g_cnt[ei[NE + e]], 1);
}
__global__ void k_dinv() {
    int i = blockIdx.x * blockDim.x + threadIdx.x;
    if (i < NN) g_dinv[i] = rsqrtf((float)(g_cnt[i] + 1));
}
__global__ void k_scan() {
    __shared__ int sm[1024];
    int t = threadIdx.x;
    int v[10]; int loc = 0;
#pragma unroll
    for (int u = 0; u < 10; u++) {
        int idx = t * 10 + u;
        v[u] = (idx < NN) ? g_cnt[idx] : 0;
        loc += v[u];
    }
    sm[t] = loc; __syncthreads();
    for (int off = 1; off < 1024; off <<= 1) {
        int add = (t >= off) ? sm[t - off] : 0;
        __syncthreads();
        sm[t] += add;
        __syncthreads();
    }
    int run = sm[t] - loc;
#pragma unroll
    for (int u = 0; u < 10; u++) {
        int idx = t * 10 + u;
        if (idx < NN) { g_rowptr[idx] = run; run += v[u]; }
    }
    if (t == 0) g_rowptr[NN] = NE;
}
__global__ void k_fillidx(const int* __restrict__ ei) {
    int e = blockIdx.x * blockDim.x + threadIdx.x;
    if (e >= NE) return;
    int c = ei[NE + e];
    int p = atomicAdd(&g_fill[c], 1);
    g_eid[g_rowptr[c] + p] = e;
}
// deterministic per-node ordering: sort edge ids ascending
__global__ void k_sortnode(const int* __restrict__ ei) {
    int i = blockIdx.x * blockDim.x + threadIdx.x;
    if (i >= NN) return;
    int s = g_rowptr[i], d = g_rowptr[i + 1] - s;
    if (d <= 128) {
        int ids[128];
        for (int q = 0; q < d; q++) ids[q] = g_eid[s + q];
        for (int q = 1; q < d; q++) {
            int key = ids[q], p = q - 1;
            while (p >= 0 && ids[p] > key) { ids[p + 1] = ids[p]; p--; }
            ids[p + 1] = key;
        }
        for (int q = 0; q < d; q++) g_eid[s + q] = ids[q];
    } else {
        for (int q = 1; q < d; q++) {
            int key = g_eid[s + q], p = q - 1;
            while (p >= 0 && g_eid[s + p] > key) { g_eid[s + p + 1] = g_eid[s + p]; p--; }
            g_eid[s + p + 1] = key;
        }
    }
    float di = g_dinv[i];
    for (int q = 0; q < d; q++) {
        int e = g_eid[s + q];
        int r = ei[e];
        g_src[s + q] = r;
        g_val[s + q] = g_dinv[r] * di;
    }
}
// edge embed over edge-row range [e0, e0+ecnt)
__global__ void k_edge_embed(const float* __restrict__ attr,
                             const float* __restrict__ w,
                             const float* __restrict__ b, int e0, int ecnt) {
    int idx = blockIdx.x * blockDim.x + threadIdx.x;
    if (idx >= ecnt * LDIM) return;
    int e = e0 + (idx >> 5), j = idx & 31;
    float a0 = attr[e * 3 + 0], a1 = attr[e * 3 + 1], a2 = attr[e * 3 + 2];
    float s = b[j] + a0 * w[j] + a1 * w[32 + j] + a2 * w[64 + j];
    g_bufA[(size_t)e * PAD + j] = __float2half_rn(s);
}
// Weights -> NGRP fp16 copies via error-feedback rounding (group means -> w),
// transposed [n][k], padded to 320.
__global__ void k_prepB(const float* __restrict__ gcn0_w, const float* __restrict__ gcn_w) {
    int idx = blockIdx.x * blockDim.x + threadIdx.x;   // 5*320*320
    if (idx >= 5 * PAD * PAD) return;
    int l   = idx / (PAD * PAD);
    int rem = idx % (PAD * PAD);
    int n   = rem / PAD;
    int k   = rem % PAD;
    int kt  = (l == 0) ? LDIM : HID;
    float w = 0.f;
    if (k < kt && n < HID)
        w = (l == 0) ? gcn0_w[k * HID + n]
                     : gcn_w[(size_t)(l - 1) * HID * HID + k * HID + n];
    float e = 0.f;
    size_t off = (size_t)l * PAD * PAD + (size_t)n * PAD + k;
#pragma unroll
    for (int g = 0; g < NGRP; g++) {
        float t = w + e;
        __half h = __float2half_rn(t);
        e = t - __half2float(h);
        g_BT[(size_t)g * 5 * PAD * PAD + off] = h;
    }
}

// ---------------- fp16 mma.sync GEMM (group-rounded weights) ----------------
// BM=128, BN=160, grid (2, mblks): n-block FAST (A dedups in L2).
// Weight copy = (mblk + layer) & 15 (error decorrelation).
// K-chunk = 64 halves (4 k16-steps): 80 MMAs per warp per sync boundary
// (2x R16) -> amortizes LDSM bursts + barrier drain.  2-stage cp.async.
#define AW_STR   36                      // 64 halves + 8 pad (bank-safe)
#define A_ST     (128 * AW_STR)          // 4608 words per A stage
#define B_BASE   (2 * A_ST)              // 9216
#define B_ST     (160 * AW_STR)          // 5760 words per B stage
#define SMW      (B_BASE + 2 * B_ST)     // 20736 words = 82944 B
#define GSTRIDE  ((size_t)5 * PAD * PAD)

__global__ __launch_bounds__(256, 2)
void k_gemm(const __half* __restrict__ A, const __half* __restrict__ BT,
            const float* __restrict__ bias, __half* __restrict__ out,
            int Ksteps, int mblk0, int lidx) {
    extern __shared__ uint32_t smu[];
    const uint32_t sb = smem_u32(smu);
    const int tid  = threadIdx.x;
    const int wid  = tid >> 5, lane = tid & 31;
    const int wm   = wid & 3, wn = wid >> 2;
    const int mblk = (int)blockIdx.y + mblk0;
    const size_t m0 = (size_t)mblk * 128;
    const int    n0 = blockIdx.x * 160;
    const __half* B = BT + (size_t)((mblk + lidx) & (NGRP - 1)) * GSTRIDE
                         + (size_t)lidx * PAD * PAD;
    const int NC = (Ksteps + 3) >> 2;           // chunks of 4 k16-steps

    float acc[2][10][4];
#pragma unroll
    for (int t = 0; t < 2; t++)
#pragma unroll
        for (int j = 0; j < 10; j++)
#pragma unroll
            for (int q = 0; q < 4; q++) acc[t][j][q] = 0.f;

    // ldmatrix per-thread offsets (bytes, relative to stage base)
    const int g = lane >> 3, l7 = lane & 7;
    uint32_t aoff[2], boff[5];
#pragma unroll
    for (int t = 0; t < 2; t++)
        aoff[t] = 4u * ((wm * 32 + t * 16 + (g & 1) * 8 + l7) * AW_STR + (g >> 1) * 4);
#pragma unroll
    for (int jp = 0; jp < 5; jp++)
        boff[jp] = 4u * ((wn * 80 + jp * 16 + (g >> 1) * 8 + l7) * AW_STR + (g & 1) * 4);

    // cp.async: A 128x8=1024 segs (4/thread), B 160x8=1280 segs (5/thread)
    auto issue = [&](int st, int c) {
        int k0 = c * 64;
        uint32_t ab = sb + (uint32_t)(st * A_ST) * 4;
#pragma unroll
        for (int u = 0; u < 4; u++) {
            int s = tid + u * 256;
            int row = s >> 3, seg = s & 7;
            cp16(ab + (uint32_t)(row * AW_STR + seg * 4) * 4,
                 A + (m0 + row) * PAD + k0 + seg * 8);
        }
        uint32_t bb = sb + (uint32_t)(B_BASE + st * B_ST) * 4;
#pragma unroll
        for (int u = 0; u < 5; u++) {
            int s = tid + u * 256;
            int row = s >> 3, seg = s & 7;
            cp16(bb + (uint32_t)(row * AW_STR + seg * 4) * 4,
                 B + (size_t)(n0 + row) * PAD + k0 + seg * 8);
        }
        CP_COMMIT();
    };

    auto compute = [&](int st, int nks) {
        uint32_t ab = sb + (uint32_t)(st * A_ST) * 4;
        uint32_t bb = sb + (uint32_t)(B_BASE + st * B_ST) * 4;
#pragma unroll
        for (int ks = 0; ks < 4; ks++) {
            if (ks >= nks) break;
            uint32_t ko = (uint32_t)ks * 32;   // 16 halves = 32 bytes
            uint32_t af[2][4];
            LDSM4(af[0][0], af[0][1], af[0][2], af[0][3], ab + aoff[0] + ko);
            LDSM4(af[1][0], af[1][1], af[1][2], af[1][3], ab + aoff[1] + ko);
            uint32_t bf[10][2];
#pragma unroll
            for (int jp = 0; jp < 5; jp++)
                LDSM4(bf[2 * jp][0], bf[2 * jp][1], bf[2 * jp + 1][0], bf[2 * jp + 1][1],
                      bb + boff[jp] + ko);
#pragma unroll
            for (int t = 0; t < 2; t++)
#pragma unroll
                for (int j = 0; j < 10; j++)
                    MMA_F16(acc[t][j], af[t], bf[j]);
        }
    };

    issue(0, 0);
    for (int c = 0; c < NC; c++) {
        if (c + 1 < NC) { issue((c + 1) & 1, c + 1); CP_WAIT(1); }
        else            { CP_WAIT(0); }
        __syncthreads();
        compute(c & 1, Ksteps - 4 * c);
        __syncthreads();
    }

    // ---- epilogue ----
    const int lr = lane >> 2, lc = lane & 3;
#pragma unroll
    for (int t = 0; t < 2; t++) {
        size_t r0 = m0 + wm * 32 + t * 16 + lr;
        size_t r1 = r0 + 8;
        bool nd0 = r0 < NN, nd1 = r1 < NN;
        float sn0 = 1.f, sn1 = 1.f;
        if (nd0) { float dv = g_dinv[r0]; sn0 = dv * dv; }
        if (nd1) { float dv = g_dinv[r1]; sn1 = dv * dv; }
#pragma unroll
        for (int j = 0; j < 10; j++) {
            int col = n0 + wn * 80 + j * 8 + lc * 2;
            float b0 = (col     < HID) ? bias[col]     : 0.f;
            float b1 = (col + 1 < HID) ? bias[col + 1] : 0.f;
            float c0 = acc[t][j][0], c1 = acc[t][j][1];
            float c2 = acc[t][j][2], c3 = acc[t][j][3];
            float o0 = fmaf(sn0, c0, b0), o1 = fmaf(sn0, c1, b1);
            float o2 = fmaf(sn1, c2, b0), o3 = fmaf(sn1, c3, b1);
            if (!nd0) { o0 = fmaxf(o0, 0.f); o1 = fmaxf(o1, 0.f); }
            if (!nd1) { o2 = fmaxf(o2, 0.f); o3 = fmaxf(o3, 0.f); }
            *(__half2*)(out + r0 * PAD + col) = __floats2half2_rn(o0, o1);
            *(__half2*)(out + r1 * PAD + col) = __floats2half2_rn(o2, o3);
            if (nd0) *(float2*)(g_hwS + r0 * PAD + col) = make_float2(c0, c1);
            if (nd1) *(float2*)(g_hwS + r1 * PAD + col) = make_float2(c2, c3);
        }
    }
}

// -------- CSR gather: out[node] = relu(out[node] + sum val * hw[src]) --------
__global__ __launch_bounds__(256)
void k_gather(__half* __restrict__ out) {
    int w = (blockIdx.x * 256 + threadIdx.x) >> 5;
    int lane = threadIdx.x & 31;
    if (w >= NN * 10) return;
    int node = w / 10, seg = w % 10;
    int j = seg * 32 + lane;
    int s = g_rowptr[node], e = g_rowptr[node + 1];
    float acc = __half2float(out[(size_t)node * PAD + j]);
    for (int p = s; p < e; p++)
        acc = fmaf(g_val[p], g_hwS[(size_t)g_src[p] * PAD + j], acc);
    out[(size_t)node * PAD + j] = __float2half_rn(fmaxf(acc, 0.f));
}

// ---------------- readout ----------------
__global__ void k_mean(const __half* __restrict__ h) {
    int j = threadIdx.x;  // 320
    size_t r0 = (size_t)blockIdx.x * 256;
    float acc = 0.f;
    for (int r = 0; r < 256; r++)
        acc += fmaxf(__half2float(h[(r0 + r) * PAD + j]), 0.f);
    g_part[blockIdx.x * PAD + j] = acc;
}
__global__ void k_head(const float* __restrict__ w1, const float* __restrict__ b1,
                       const float* __restrict__ w2, const float* __restrict__ b2,
                       float* __restrict__ out) {
    __shared__ float g[PAD];
    __shared__ float t1[32];
    int t = threadIdx.x;  // 320
    if (t < PAD) {
        float s = 0.f;
        for (int b = 0; b < 625; b++) s += g_part[b * PAD + t];
        g[t] = s * (1.0f / (float)MRWS);
    }
    __syncthreads();
    if (t < 32) {
        float a = b1[t];
        for (int j = 0; j < HID; j++) a = fmaf(g[j], w1[j * 32 + t], a);
        t1[t] = fmaxf(a, 0.f);
    }
    __syncthreads();
    if (t < 2) {
        float a = b2[t];
        for (int k = 0; k < 32; k++) a = fmaf(t1[k], w2[k * 2 + t], a);
        out[t] = a;
    }
}

// ---------------- launch ----------------
extern "C" void kernel_launch(void* const* d_in, const int* in_sizes, int n_in,
                              void* d_out, int out_size) {
    const int*   ei        = (const int*)d_in[1];
    const float* edge_attr = (const float*)d_in[2];
    const float* edge_w    = (const float*)d_in[6];
    const float* edge_b    = (const float*)d_in[7];
    const float* gcn0_w    = (const float*)d_in[8];
    const float* gcn0_b    = (const float*)d_in[9];
    const float* gcn_w     = (const float*)d_in[10];
    const float* gcn_b     = (const float*)d_in[11];
    const float* lin1_w    = (const float*)d_in[12];
    const float* lin1_b    = (const float*)d_in[13];
    const float* lin2_w    = (const float*)d_in[14];
    const float* lin2_b    = (const float*)d_in[15];
    float* out = (float*)d_out;

    // one-time host infra (streams/events; no device memory)
    static cudaStream_t sB = nullptr;
    static cudaEvent_t evFork = nullptr, evJoin = nullptr;
    if (!sB) {
        cudaStreamCreateWithFlags(&sB, cudaStreamNonBlocking);
        cudaEventCreateWithFlags(&evFork, cudaEventDisableTiming);
        cudaEventCreateWithFlags(&evJoin, cudaEventDisableTiming);
        cudaFuncSetAttribute(k_gemm, cudaFuncAttributeMaxDynamicSharedMemorySize, SMW * 4);
    }

    __half *bufA = nullptr, *bufB = nullptr, *bt = nullptr;
    cudaGetSymbolAddress((void**)&bufA, g_bufA);
    cudaGetSymbolAddress((void**)&bufB, g_bufB);
    cudaGetSymbolAddress((void**)&bt, g_BT);

    const int EHI = NE - LOWROW;                      // 149888 high edges

    // --- shared prologue on capture stream: weights (needed by both chains) ---
    k_prepB<<<2000, 256>>>(gcn0_w, gcn_w);

    // --- fork: high chain (rows >= LOWROW) on sB ---
    cudaEventRecord(evFork, 0);
    cudaStreamWaitEvent(sB, evFork, 0);

    k_edge_embed<<<(EHI * LDIM + 255) / 256, 256, 0, sB>>>(edge_attr, edge_w, edge_b,
                                                           LOWROW, EHI);
    {
        dim3 ghi(2, 1250 - LOWBLK);
        k_gemm<<<ghi, 256, SMW * 4, sB>>>(bufA, bt, gcn0_b, bufB, 2, LOWBLK, 0);
        for (int l = 1; l < 5; l++) {
            const __half* in = (l & 1) ? bufB : bufA;
            __half*       o  = (l & 1) ? bufA : bufB;
            k_gemm<<<ghi, 256, SMW * 4, sB>>>(in, bt, gcn_b + (size_t)(l - 1) * HID,
                                              o, 19, LOWBLK, l);
        }
    }
    cudaEventRecord(evJoin, sB);

    // --- low chain (rows < LOWROW) + CSR machinery on capture stream ---
    k_init<<<40, 256>>>();
    k_count<<<625, 256>>>(ei);
    k_dinv<<<40, 256>>>();
    k_scan<<<1, 1024>>>();
    k_fillidx<<<625, 256>>>(ei);
    k_sortnode<<<40, 256>>>(ei);
    k_edge_embed<<<(LOWROW * LDIM + 255) / 256, 256>>>(edge_attr, edge_w, edge_b,
                                                       0, LOWROW);
    {
        dim3 glo(2, LOWBLK);
        k_gemm<<<glo, 256, SMW * 4>>>(bufA, bt, gcn0_b, bufB, 2, 0, 0);
        k_gather<<<12500, 256>>>(bufB);
        for (int l = 1; l < 5; l++) {
            const __half* in = (l & 1) ? bufB : bufA;
            __half*       o  = (l & 1) ? bufA : bufB;
            k_gemm<<<glo, 256, SMW * 4>>>(in, bt, gcn_b + (size_t)(l - 1) * HID,
                                          o, 19, 0, l);
            k_gather<<<12500, 256>>>(o);
        }
    }

    // --- join and readout ---
    cudaStreamWaitEvent(0, evJoin, 0);
    k_mean<<<625, 320>>>(bufB);
    k_head<<<1, 320>>>(lin1_w, lin1_b, lin2_w, lin2_b, out);
}